// round 12
// baseline (speedup 1.0000x reference)
#include <cuda_runtime.h>
#include <cuda_fp16.h>
#include <cuda_bf16.h>
#include <math.h>

#define BB 64
#define TT 512
#define NN 256
#define DD 128
#define LOG_2PI_F 1.8378770664093453f
#define LN2_F 0.6931471805599453f

// ---------------- device scratch (static globals; no allocs) ----------------
static __device__ float          E_sc[BB * TT * NN];   // emission logprobs [B*T, N] fp32 (unshifted)
static __device__ float          M_sc[BB * TT];        // per-row max of E
static __device__ __nv_bfloat162 AhT_g[(NN / 2) * NN]; // packed A^T bf16: [k][j] = (A[2k][j], A[2k+1][j])
static __device__ __half2        WpT_g[DD * NN];       // [d][n] = (-0.5*iv, mu*iv) as half2
static __device__ float          cvec_g[NN];           // -0.5 * sum_d (mu^2*iv + log_var + LOG2PI)
static __device__ float          logpi_g[NN];
static __device__ float          logprop_g[BB];

// order-preserving float<->uint map for REDUX-based fp max (handles negatives)
__device__ __forceinline__ float warp_max_f(float x) {
    unsigned u = __float_as_uint(x);
    u = ((int)u >= 0) ? (u ^ 0x80000000u) : ~u;
    u = __reduce_max_sync(0xffffffffu, u);
    return ((int)u < 0) ? __uint_as_float(u ^ 0x80000000u) : __uint_as_float(~u);
}

// ---------------- merged prep kernel ----------------
__global__ void prep_all(const float* __restrict__ trans, const float* __restrict__ pri,
                         const float* __restrict__ mu, const float* __restrict__ lv) {
    __shared__ float redA[8], redB[8];
    int bid = blockIdx.x, t = threadIdx.x;
    int wid = t >> 5, lane = t & 31;

    if (bid < 128) {
        int k = bid;
        float v0 = trans[(2 * k) * NN + t];
        float v1 = trans[(2 * k + 1) * NN + t];
        float m0 = v0, m1 = v1;
#pragma unroll
        for (int o = 16; o; o >>= 1) {
            m0 = fmaxf(m0, __shfl_xor_sync(0xffffffffu, m0, o));
            m1 = fmaxf(m1, __shfl_xor_sync(0xffffffffu, m1, o));
        }
        if (lane == 0) { redA[wid] = m0; redB[wid] = m1; }
        __syncthreads();
        float mb0 = redA[0], mb1 = redB[0];
#pragma unroll
        for (int w = 1; w < 8; w++) { mb0 = fmaxf(mb0, redA[w]); mb1 = fmaxf(mb1, redB[w]); }
        __syncthreads();
        float e0 = expf(v0 - mb0), e1 = expf(v1 - mb1);
        float s0 = e0, s1 = e1;
#pragma unroll
        for (int o = 16; o; o >>= 1) {
            s0 += __shfl_xor_sync(0xffffffffu, s0, o);
            s1 += __shfl_xor_sync(0xffffffffu, s1, o);
        }
        if (lane == 0) { redA[wid] = s0; redB[wid] = s1; }
        __syncthreads();
        float S0 = 0.f, S1 = 0.f;
#pragma unroll
        for (int w = 0; w < 8; w++) { S0 += redA[w]; S1 += redB[w]; }
        AhT_g[k * NN + t] = __floats2bfloat162_rn(e0 / S0, e1 / S1);
    } else if (bid == 128) {
        float v = pri[t];
        float m = v;
#pragma unroll
        for (int o = 16; o; o >>= 1) m = fmaxf(m, __shfl_xor_sync(0xffffffffu, m, o));
        if (lane == 0) redA[wid] = m;
        __syncthreads();
        float mb = redA[0];
#pragma unroll
        for (int w = 1; w < 8; w++) mb = fmaxf(mb, redA[w]);
        __syncthreads();
        float e = expf(v - mb);
        float s = e;
#pragma unroll
        for (int o = 16; o; o >>= 1) s += __shfl_xor_sync(0xffffffffu, s, o);
        if (lane == 0) redA[wid] = s;
        __syncthreads();
        float S = 0.f;
#pragma unroll
        for (int w = 0; w < 8; w++) S += redA[w];
        logpi_g[t] = (v - mb) - logf(S);
    } else {
        int wb = bid - 129;
        int n = 2 * wb + (t >> 7);
        int d = t & 127;
        float l = lv[n * DD + d];
        float m = mu[n * DD + d];
        float iv = expf(-l);
        WpT_g[d * NN + n] = __floats2half2_rn(-0.5f * iv, m * iv);
        float c = m * m * iv + l + LOG_2PI_F;
#pragma unroll
        for (int o = 16; o; o >>= 1) c += __shfl_xor_sync(0xffffffffu, c, o);
        if (lane == 0) redA[wid] = c;
        __syncthreads();
        if ((t & 127) == 0) {
            int base = (t >> 7) * 4;
            float s = redA[base] + redA[base + 1] + redA[base + 2] + redA[base + 3];
            cvec_g[n] = -0.5f * s;
        }
    }
}

// ---------------- emission GEMM (R8 structure) + row-max epilogue ----------------
// thread: ib = tid&1 (d-range [64*ib, 64*ib+64)), nb = tid>>1 (cols 2nb, 2nb+1).
__global__ void __launch_bounds__(256, 1) emis_kernel(const float* __restrict__ X) {
    __shared__ __align__(16) __half2 xp[32 * DD];      // (x^2, x) per [m][d], 16 KB
    __shared__ __align__(16) float redM[32][8];        // per-row warp maxes
    int tid = threadIdx.x;
    int r0 = blockIdx.x * 32;
    int ib = tid & 1, nb = tid >> 1;
    int wid = tid >> 5, lane = tid & 31;

#pragma unroll
    for (int it = 0; it < 16; it++) {
        int idx = it * 256 + tid;
        int m = idx >> 7, d = idx & 127;
        float x = X[(r0 + m) * DD + d];
        xp[idx] = __floats2half2_rn(x * x, x);
    }

    __half2 w0[64], w1[64];
#pragma unroll
    for (int k = 0; k < 64; k++) {
        w0[k] = WpT_g[(64 * ib + k) * NN + 2 * nb];
        w1[k] = WpT_g[(64 * ib + k) * NN + 2 * nb + 1];
    }
    float cn = cvec_g[tid];
    __syncthreads();

    for (int m = 0; m < 32; m++) {
        const float4* xr = reinterpret_cast<const float4*>(xp + m * DD + 64 * ib);
        __half2 c0a = __float2half2_rn(0.f), c0b = c0a, c1a = c0a, c1b = c0a;
#pragma unroll
        for (int q = 0; q < 16; q++) {
            float4 v = xr[q];
            const __half2* xv = reinterpret_cast<const __half2*>(&v);
            c0a = __hfma2(w0[4 * q + 0], xv[0], c0a);
            c1a = __hfma2(w1[4 * q + 0], xv[0], c1a);
            c0b = __hfma2(w0[4 * q + 1], xv[1], c0b);
            c1b = __hfma2(w1[4 * q + 1], xv[1], c1b);
            c0a = __hfma2(w0[4 * q + 2], xv[2], c0a);
            c1a = __hfma2(w1[4 * q + 2], xv[2], c1a);
            c0b = __hfma2(w0[4 * q + 3], xv[3], c0b);
            c1b = __hfma2(w1[4 * q + 3], xv[3], c1b);
        }
        float2 f0 = __half22float2(__hadd2(c0a, c0b));
        float2 f1 = __half22float2(__hadd2(c1a, c1b));
        float S0 = f0.x + f0.y, S1 = f1.x + f1.y;
        S0 += __shfl_xor_sync(0xffffffffu, S0, 1);
        S1 += __shfl_xor_sync(0xffffffffu, S1, 1);
        float val = (ib ? S1 : S0) + cn;
        E_sc[(r0 + m) * NN + tid] = val;               // coalesced over tid
        float mm = warp_max_f(val);                    // warp REDUX, no barrier
        if (lane == 0) redM[m][wid] = mm;
    }
    __syncthreads();
    if (tid < 32) {
        float4 q0 = *reinterpret_cast<const float4*>(&redM[tid][0]);
        float4 q1 = *reinterpret_cast<const float4*>(&redM[tid][4]);
        float M = fmaxf(fmaxf(fmaxf(q0.x, q0.y), fmaxf(q0.z, q0.w)),
                        fmaxf(fmaxf(q1.x, q1.y), fmaxf(q1.z, q1.w)));
        M_sc[r0 + tid] = M;
    }
}

// ---------------- forward recursion: deterministic normalization ----------------
// p_j(t) = exp(E[t,j] - M[t]) * S_j,  S_j = sum_i p_i(t-1) A_ij,  mhat += M[t].
// No per-step max/log; ONE barrier per step (double-buffered p in bf16).
// Exponent-only renorm staged at t=0,4,8,... (warp REDUX, lane0 -> redu),
// applied exactly (power of two) at t=1,5,9,...; mhat absorbs e2*ln2.
__global__ void __launch_bounds__(256, 1) forward_rec() {
    __shared__ __align__(16) __nv_bfloat16 psm[2 * NN];
    __shared__ __align__(16) unsigned redu[8];
    __shared__ float red[8];
    int b = blockIdx.x, tid = threadIdx.x;
    int wid = tid >> 5, lane = tid & 31;
    int ib = tid & 1, jb = tid >> 1;

    // A tiles (bf16): pair index k covers i = 128*ib + 2k, 2k+1; cols 2jb, 2jb+1
    __nv_bfloat162 a0[64], a1[64];
#pragma unroll
    for (int k = 0; k < 64; k++) {
        a0[k] = AhT_g[(64 * ib + k) * NN + 2 * jb];
        a1[k] = AhT_g[(64 * ib + k) * NN + 2 * jb + 1];
    }

    const float* __restrict__ Erow = E_sc + b * TT * NN;
    const float* __restrict__ Mrow = M_sc + b * TT;

    // t = 0: p = exp(logpi + E0 - M0), mhat = M0. Stage renorm for t=1.
    float M0 = Mrow[0];
    float p = __expf(logpi_g[tid] + Erow[tid] - M0);
    float mhat = M0;
    psm[tid] = __float2bfloat16(p);                    // buffer 0
    {
        unsigned pb = __reduce_max_sync(0xffffffffu, __float_as_uint(p));
        if (lane == 0) redu[wid] = pb;                 // p > 0: bits compare as uint
    }
    int cur = 0;
    float e_next = Erow[1 * NN + tid];
    float Mn = Mrow[1];
    __syncthreads();                                   // orders psm + redu for t=1

    const __nv_bfloat162 bzero = __float2bfloat162_rn(0.f);

    for (int t = 1; t < TT; t++) {
        float e = e_next;
        float Mt = Mn;
        if (t + 1 < TT) { e_next = Erow[(t + 1) * NN + tid]; Mn = Mrow[t + 1]; }

        // renorm application (staged at t-1 = 0,4,8,...)
        float rescale = 1.0f;
        if (((t - 1) & 3) == 0) {
            uint4 u0 = *reinterpret_cast<const uint4*>(redu);
            uint4 u1 = *reinterpret_cast<const uint4*>(redu + 4);
            unsigned pm = max(max(max(u0.x, u0.y), max(u0.z, u0.w)),
                              max(max(u1.x, u1.y), max(u1.z, u1.w)));
            int e2 = (int)(pm >> 23) - 127;            // exponent of block-max p
            rescale = __uint_as_float((unsigned)(127 - e2) << 23);   // 2^-e2 (exact)
            mhat += (float)e2 * LN2_F;
        }

        // matvec partials over i-range [128*ib, 128*ib+128) from psm[cur]
        const float4* p4 = reinterpret_cast<const float4*>(psm + cur * NN + 128 * ib);
        __nv_bfloat162 c0a = bzero, c0b = bzero, c1a = bzero, c1b = bzero;
#pragma unroll
        for (int q = 0; q < 16; q++) {
            float4 v = p4[q];
            const __nv_bfloat162* pv = reinterpret_cast<const __nv_bfloat162*>(&v);
            c0a = __hfma2(a0[4 * q + 0], pv[0], c0a);
            c1a = __hfma2(a1[4 * q + 0], pv[0], c1a);
            c0b = __hfma2(a0[4 * q + 1], pv[1], c0b);
            c1b = __hfma2(a1[4 * q + 1], pv[1], c1b);
            c0a = __hfma2(a0[4 * q + 2], pv[2], c0a);
            c1a = __hfma2(a1[4 * q + 2], pv[2], c1a);
            c0b = __hfma2(a0[4 * q + 3], pv[3], c0b);
            c1b = __hfma2(a1[4 * q + 3], pv[3], c1b);
        }
        float2 f0 = __bfloat1622float2(__hadd2(c0a, c0b));
        float2 f1 = __bfloat1622float2(__hadd2(c1a, c1b));
        float S0 = f0.x + f0.y, S1 = f1.x + f1.y;
        S0 += __shfl_xor_sync(0xffffffffu, S0, 1);     // combine i-halves
        S1 += __shfl_xor_sync(0xffffffffu, S1, 1);
        float S = ib ? S1 : S0;

        p = __expf(e - Mt) * S * rescale;              // no log, no max reduction
        mhat += Mt;

        if ((t & 3) == 0) {                            // stage renorm for step t+1
            unsigned pb = __reduce_max_sync(0xffffffffu, __float_as_uint(p));
            if (lane == 0) redu[wid] = pb;
        }
        psm[(cur ^ 1) * NN + tid] = __float2bfloat16(p);
        __syncthreads();                               // ONE barrier per step
        cur ^= 1;
    }

    // log_prop[b] = mhat + log(sum_j p_j)
    float s = p;
#pragma unroll
    for (int o = 16; o; o >>= 1) s += __shfl_xor_sync(0xffffffffu, s, o);
    if (lane == 0) red[wid] = s;
    __syncthreads();
    if (tid == 0) {
        float tot = 0.f;
#pragma unroll
        for (int w = 0; w < 8; w++) tot += red[w];
        logprop_g[b] = mhat + __logf(tot);
    }
}

// ---------------- final: sum log_props over batch ----------------
__global__ void finalize_kernel(float* __restrict__ out) {
    __shared__ float red[2];
    int t = threadIdx.x;
    float v = logprop_g[t];
#pragma unroll
    for (int o = 16; o; o >>= 1) v += __shfl_xor_sync(0xffffffffu, v, o);
    if ((t & 31) == 0) red[t >> 5] = v;
    __syncthreads();
    if (t == 0) out[0] = red[0] + red[1];
}

// ---------------- launch ----------------
extern "C" void kernel_launch(void* const* d_in, const int* in_sizes, int n_in,
                              void* d_out, int out_size) {
    (void)in_sizes; (void)n_in; (void)out_size;
    const float* X     = (const float*)d_in[0];
    const float* mu    = (const float*)d_in[1];
    const float* lv    = (const float*)d_in[2];
    const float* trans = (const float*)d_in[3];
    const float* pri   = (const float*)d_in[4];
    float* out = (float*)d_out;

    prep_all<<<257, 256>>>(trans, pri, mu, lv);
    emis_kernel<<<(BB * TT) / 32, 256>>>(X);
    forward_rec<<<BB, 256>>>();
    finalize_kernel<<<1, 64>>>(out);
}

// round 14
// speedup vs baseline: 1.4140x; 1.4140x over previous
#include <cuda_runtime.h>
#include <cuda_fp16.h>
#include <cuda_bf16.h>
#include <math.h>

#define BB 64
#define TT 512
#define NN 256
#define DD 128
#define LOG_2PI_F 1.8378770664093453f
#define LN2_F 0.6931471805599453f

// parallel-in-time split: chunk0 records t=0..SPLIT-1, chunk1 warms from T0 and records SPLIT..TT-1
#define SPLIT 276
#define T0    236        // SPLIT-40 warm-up steps; divisible by 4 (renorm alignment)

// ---------------- device scratch (static globals; no allocs) ----------------
static __device__ float          E_sc[BB * TT * NN];   // emission logprobs [B*T, N] fp32 (unshifted)
static __device__ float          M_sc[BB * TT];        // per-row max of E
static __device__ __nv_bfloat162 AhT_g[(NN / 2) * NN]; // packed A^T bf16: [k][j] = (A[2k][j], A[2k+1][j])
static __device__ __half2        WpT_g[DD * NN];       // [d][n] = (-0.5*iv, mu*iv) as half2
static __device__ float          cvec_g[NN];           // -0.5 * sum_d (mu^2*iv + log_var + LOG2PI)
static __device__ float          logpi_g[NN];
static __device__ float          logprop_g[BB];        // chunk0: log P(X_{0:SPLIT-1})
static __device__ float          logprop2_g[BB];       // chunk1: ~log P(X_{SPLIT:TT-1} | past)

// order-preserving float<->uint map for REDUX-based fp max (handles negatives)
__device__ __forceinline__ float warp_max_f(float x) {
    unsigned u = __float_as_uint(x);
    u = ((int)u >= 0) ? (u ^ 0x80000000u) : ~u;
    u = __reduce_max_sync(0xffffffffu, u);
    return ((int)u < 0) ? __uint_as_float(u ^ 0x80000000u) : __uint_as_float(~u);
}

// ---------------- merged prep kernel ----------------
__global__ void prep_all(const float* __restrict__ trans, const float* __restrict__ pri,
                         const float* __restrict__ mu, const float* __restrict__ lv) {
    __shared__ float redA[8], redB[8];
    int bid = blockIdx.x, t = threadIdx.x;
    int wid = t >> 5, lane = t & 31;

    if (bid < 128) {
        int k = bid;
        float v0 = trans[(2 * k) * NN + t];
        float v1 = trans[(2 * k + 1) * NN + t];
        float m0 = v0, m1 = v1;
#pragma unroll
        for (int o = 16; o; o >>= 1) {
            m0 = fmaxf(m0, __shfl_xor_sync(0xffffffffu, m0, o));
            m1 = fmaxf(m1, __shfl_xor_sync(0xffffffffu, m1, o));
        }
        if (lane == 0) { redA[wid] = m0; redB[wid] = m1; }
        __syncthreads();
        float mb0 = redA[0], mb1 = redB[0];
#pragma unroll
        for (int w = 1; w < 8; w++) { mb0 = fmaxf(mb0, redA[w]); mb1 = fmaxf(mb1, redB[w]); }
        __syncthreads();
        float e0 = expf(v0 - mb0), e1 = expf(v1 - mb1);
        float s0 = e0, s1 = e1;
#pragma unroll
        for (int o = 16; o; o >>= 1) {
            s0 += __shfl_xor_sync(0xffffffffu, s0, o);
            s1 += __shfl_xor_sync(0xffffffffu, s1, o);
        }
        if (lane == 0) { redA[wid] = s0; redB[wid] = s1; }
        __syncthreads();
        float S0 = 0.f, S1 = 0.f;
#pragma unroll
        for (int w = 0; w < 8; w++) { S0 += redA[w]; S1 += redB[w]; }
        AhT_g[k * NN + t] = __floats2bfloat162_rn(e0 / S0, e1 / S1);
    } else if (bid == 128) {
        float v = pri[t];
        float m = v;
#pragma unroll
        for (int o = 16; o; o >>= 1) m = fmaxf(m, __shfl_xor_sync(0xffffffffu, m, o));
        if (lane == 0) redA[wid] = m;
        __syncthreads();
        float mb = redA[0];
#pragma unroll
        for (int w = 1; w < 8; w++) mb = fmaxf(mb, redA[w]);
        __syncthreads();
        float e = expf(v - mb);
        float s = e;
#pragma unroll
        for (int o = 16; o; o >>= 1) s += __shfl_xor_sync(0xffffffffu, s, o);
        if (lane == 0) redA[wid] = s;
        __syncthreads();
        float S = 0.f;
#pragma unroll
        for (int w = 0; w < 8; w++) S += redA[w];
        logpi_g[t] = (v - mb) - logf(S);
    } else {
        int wb = bid - 129;
        int n = 2 * wb + (t >> 7);
        int d = t & 127;
        float l = lv[n * DD + d];
        float m = mu[n * DD + d];
        float iv = expf(-l);
        WpT_g[d * NN + n] = __floats2half2_rn(-0.5f * iv, m * iv);
        float c = m * m * iv + l + LOG_2PI_F;
#pragma unroll
        for (int o = 16; o; o >>= 1) c += __shfl_xor_sync(0xffffffffu, c, o);
        if (lane == 0) redA[wid] = c;
        __syncthreads();
        if ((t & 127) == 0) {
            int base = (t >> 7) * 4;
            float s = redA[base] + redA[base + 1] + redA[base + 2] + redA[base + 3];
            cvec_g[n] = -0.5f * s;
        }
    }
}

// ---------------- emission GEMM + row-max epilogue ----------------
__global__ void __launch_bounds__(256, 1) emis_kernel(const float* __restrict__ X) {
    __shared__ __align__(16) __half2 xp[32 * DD];
    __shared__ __align__(16) float redM[32][8];
    int tid = threadIdx.x;
    int r0 = blockIdx.x * 32;
    int ib = tid & 1, nb = tid >> 1;
    int wid = tid >> 5, lane = tid & 31;

#pragma unroll
    for (int it = 0; it < 16; it++) {
        int idx = it * 256 + tid;
        int m = idx >> 7, d = idx & 127;
        float x = X[(r0 + m) * DD + d];
        xp[idx] = __floats2half2_rn(x * x, x);
    }

    __half2 w0[64], w1[64];
#pragma unroll
    for (int k = 0; k < 64; k++) {
        w0[k] = WpT_g[(64 * ib + k) * NN + 2 * nb];
        w1[k] = WpT_g[(64 * ib + k) * NN + 2 * nb + 1];
    }
    float cn = cvec_g[tid];
    __syncthreads();

    for (int m = 0; m < 32; m++) {
        const float4* xr = reinterpret_cast<const float4*>(xp + m * DD + 64 * ib);
        __half2 c0a = __float2half2_rn(0.f), c0b = c0a, c1a = c0a, c1b = c0a;
#pragma unroll
        for (int q = 0; q < 16; q++) {
            float4 v = xr[q];
            const __half2* xv = reinterpret_cast<const __half2*>(&v);
            c0a = __hfma2(w0[4 * q + 0], xv[0], c0a);
            c1a = __hfma2(w1[4 * q + 0], xv[0], c1a);
            c0b = __hfma2(w0[4 * q + 1], xv[1], c0b);
            c1b = __hfma2(w1[4 * q + 1], xv[1], c1b);
            c0a = __hfma2(w0[4 * q + 2], xv[2], c0a);
            c1a = __hfma2(w1[4 * q + 2], xv[2], c1a);
            c0b = __hfma2(w0[4 * q + 3], xv[3], c0b);
            c1b = __hfma2(w1[4 * q + 3], xv[3], c1b);
        }
        float2 f0 = __half22float2(__hadd2(c0a, c0b));
        float2 f1 = __half22float2(__hadd2(c1a, c1b));
        float S0 = f0.x + f0.y, S1 = f1.x + f1.y;
        S0 += __shfl_xor_sync(0xffffffffu, S0, 1);
        S1 += __shfl_xor_sync(0xffffffffu, S1, 1);
        float val = (ib ? S1 : S0) + cn;
        E_sc[(r0 + m) * NN + tid] = val;
        float mm = warp_max_f(val);
        if (lane == 0) redM[m][wid] = mm;
    }
    __syncthreads();
    if (tid < 32) {
        float4 q0 = *reinterpret_cast<const float4*>(&redM[tid][0]);
        float4 q1 = *reinterpret_cast<const float4*>(&redM[tid][4]);
        float M = fmaxf(fmaxf(fmaxf(q0.x, q0.y), fmaxf(q0.z, q0.w)),
                        fmaxf(fmaxf(q1.x, q1.y), fmaxf(q1.z, q1.w)));
        M_sc[r0 + tid] = M;
    }
}

// ---------------- forward recursion, parallel-in-time (2 chunks per b) ----------------
// blocks 0..63: chunk0 (exact, t=0..SPLIT-1, prior = logpi).
// blocks 64..127: chunk1 (uniform warm start at T0; records V2-V1 across [SPLIT, TT)).
__global__ void __launch_bounds__(256, 1) forward_rec() {
    __shared__ __align__(16) __nv_bfloat16 psm[2 * NN];
    __shared__ __align__(16) unsigned redu[8];
    __shared__ float red[8];
    __shared__ float redV[8];
    bool second = blockIdx.x >= BB;
    int b = blockIdx.x & (BB - 1);
    int tid = threadIdx.x;
    int wid = tid >> 5, lane = tid & 31;
    int ib = tid & 1, jb = tid >> 1;

    __nv_bfloat162 a0[64], a1[64];
#pragma unroll
    for (int k = 0; k < 64; k++) {
        a0[k] = AhT_g[(64 * ib + k) * NN + 2 * jb];
        a1[k] = AhT_g[(64 * ib + k) * NN + 2 * jb + 1];
    }

    const float* __restrict__ Erow = E_sc + b * TT * NN;
    const float* __restrict__ Mrow = M_sc + b * TT;

    int t_init = second ? T0 : 0;
    int t_end  = second ? TT : SPLIT;

    // init: chunk0 uses prior; chunk1 uniform (constant cancels in V2-V1)
    float M0 = Mrow[t_init];
    float pl = Erow[t_init * NN + tid] - M0;
    if (!second) pl += logpi_g[tid];
    float p = __expf(pl);
    float mhat = M0;
    psm[tid] = __float2bfloat16(p);                    // buffer 0
    {
        unsigned pb = __reduce_max_sync(0xffffffffu, __float_as_uint(p));
        if (lane == 0) redu[wid] = pb;
    }
    int cur = 0;
    float e_next = Erow[(t_init + 1) * NN + tid];
    float Mn = Mrow[t_init + 1];
    float V1 = 0.f;                                    // boundary value (tid0, chunk1)
    __syncthreads();

    const __nv_bfloat162 bzero = __float2bfloat162_rn(0.f);

    for (int t = t_init + 1; t < t_end; t++) {
        float e = e_next;
        float Mt = Mn;
        if (t + 1 < t_end) { e_next = Erow[(t + 1) * NN + tid]; Mn = Mrow[t + 1]; }

        // V1 capture: redV staged at end of iteration SPLIT-1, read after its barrier
        if (second && t == SPLIT && tid == 0) {
            float tot = 0.f;
#pragma unroll
            for (int w = 0; w < 8; w++) tot += redV[w];
            V1 = mhat + __logf(tot);
        }

        // renorm application (staged at t-1 = t_init, t_init+4, ...; t_init % 4 == 0)
        float rescale = 1.0f;
        if (((t - 1) & 3) == 0) {
            uint4 u0 = *reinterpret_cast<const uint4*>(redu);
            uint4 u1 = *reinterpret_cast<const uint4*>(redu + 4);
            unsigned pm = max(max(max(u0.x, u0.y), max(u0.z, u0.w)),
                              max(max(u1.x, u1.y), max(u1.z, u1.w)));
            int e2 = (int)(pm >> 23) - 127;
            rescale = __uint_as_float((unsigned)(127 - e2) << 23);   // 2^-e2 (exact)
            mhat += (float)e2 * LN2_F;
        }

        // matvec partials over i-range [128*ib, 128*ib+128) from psm[cur]
        const float4* p4 = reinterpret_cast<const float4*>(psm + cur * NN + 128 * ib);
        __nv_bfloat162 c0a = bzero, c0b = bzero, c1a = bzero, c1b = bzero;
#pragma unroll
        for (int q = 0; q < 16; q++) {
            float4 v = p4[q];
            const __nv_bfloat162* pv = reinterpret_cast<const __nv_bfloat162*>(&v);
            c0a = __hfma2(a0[4 * q + 0], pv[0], c0a);
            c1a = __hfma2(a1[4 * q + 0], pv[0], c1a);
            c0b = __hfma2(a0[4 * q + 1], pv[1], c0b);
            c1b = __hfma2(a1[4 * q + 1], pv[1], c1b);
            c0a = __hfma2(a0[4 * q + 2], pv[2], c0a);
            c1a = __hfma2(a1[4 * q + 2], pv[2], c1a);
            c0b = __hfma2(a0[4 * q + 3], pv[3], c0b);
            c1b = __hfma2(a1[4 * q + 3], pv[3], c1b);
        }
        float2 f0 = __bfloat1622float2(__hadd2(c0a, c0b));
        float2 f1 = __bfloat1622float2(__hadd2(c1a, c1b));
        float S0 = f0.x + f0.y, S1 = f1.x + f1.y;
        S0 += __shfl_xor_sync(0xffffffffu, S0, 1);
        S1 += __shfl_xor_sync(0xffffffffu, S1, 1);
        float S = ib ? S1 : S0;

        p = __expf(e - Mt) * S * rescale;              // no log, no max reduction
        mhat += Mt;

        if ((t & 3) == 0) {                            // stage renorm for step t+1
            unsigned pb = __reduce_max_sync(0xffffffffu, __float_as_uint(p));
            if (lane == 0) redu[wid] = pb;
        }
        if (second && t == SPLIT - 1) {                // stage boundary sum for V1
            float sv = p;
#pragma unroll
            for (int o = 16; o; o >>= 1) sv += __shfl_xor_sync(0xffffffffu, sv, o);
            if (lane == 0) redV[wid] = sv;
        }
        psm[(cur ^ 1) * NN + tid] = __float2bfloat16(p);
        __syncthreads();                               // ONE barrier per step
        cur ^= 1;
    }

    // chunk total: mhat + log(sum_j p_j); chunk1 subtracts boundary V1
    float s = p;
#pragma unroll
    for (int o = 16; o; o >>= 1) s += __shfl_xor_sync(0xffffffffu, s, o);
    if (lane == 0) red[wid] = s;
    __syncthreads();
    if (tid == 0) {
        float tot = 0.f;
#pragma unroll
        for (int w = 0; w < 8; w++) tot += red[w];
        float L = mhat + __logf(tot);
        if (second) logprop2_g[b] = L - V1;
        else        logprop_g[b] = L;
    }
}

// ---------------- final: sum both chunk contributions over batch ----------------
__global__ void finalize_kernel(float* __restrict__ out) {
    __shared__ float red[2];
    int t = threadIdx.x;
    float v = logprop_g[t] + logprop2_g[t];
#pragma unroll
    for (int o = 16; o; o >>= 1) v += __shfl_xor_sync(0xffffffffu, v, o);
    if ((t & 31) == 0) red[t >> 5] = v;
    __syncthreads();
    if (t == 0) out[0] = red[0] + red[1];
}

// ---------------- launch ----------------
extern "C" void kernel_launch(void* const* d_in, const int* in_sizes, int n_in,
                              void* d_out, int out_size) {
    (void)in_sizes; (void)n_in; (void)out_size;
    const float* X     = (const float*)d_in[0];
    const float* mu    = (const float*)d_in[1];
    const float* lv    = (const float*)d_in[2];
    const float* trans = (const float*)d_in[3];
    const float* pri   = (const float*)d_in[4];
    float* out = (float*)d_out;

    prep_all<<<257, 256>>>(trans, pri, mu, lv);
    emis_kernel<<<(BB * TT) / 32, 256>>>(X);
    forward_rec<<<2 * BB, 256>>>();
    finalize_kernel<<<1, 64>>>(out);
}